// round 11
// baseline (speedup 1.0000x reference)
#include <cuda_runtime.h>
#include <cuda_fp16.h>
#include <cstdint>
#include <cstddef>

// Problem dims
#define TOKENS_N 8192
#define IN_F     4096
#define OUT_F    4096

// GEMM tiling: CTA 128x256, warp 64x64, BK=64 halves (128B/row)
#define BM      128
#define BN      256
#define BK      64
#define STAGES  3
#define NCHUNK  (IN_F / BK)            // 64

// smem: padded row stride 72 halves = 144 B (36 banks ≡ 4 mod 32 -> each
// ldmatrix 8-row phase hits banks 4r..4r+3, all 32 banks once; conflict-free)
#define ROW_BYTES    144
#define A_TILE_BYTES (BM * ROW_BYTES)                 // 18432
#define B_TILE_BYTES (BN * ROW_BYTES)                 // 36864
#define STAGE_BYTES  (A_TILE_BYTES + B_TILE_BYTES)    // 55296
#define SMEM_BYTES   (STAGES * STAGE_BYTES)           // 165888 (opt-in)

// Pre-converted operands (device globals: allowed scratch)
__device__ __half g_X [(size_t)TOKENS_N * IN_F];   // 64 MB
__device__ __half g_Wh[(size_t)OUT_F   * IN_F];    // 32 MB

#define GX_BLOCKS ((unsigned)(((size_t)TOKENS_N * IN_F / 8) / 256))   // 16384
#define GW_BLOCKS ((unsigned)(((size_t)OUT_F   * IN_F / 8) / 256))    // 8192

// ---------------------------------------------------------------------------
// helpers
// ---------------------------------------------------------------------------
__device__ __forceinline__ uint32_t smem_u32(const void* p) {
    uint32_t a;
    asm("{ .reg .u64 t; cvta.to.shared.u64 t, %1; cvt.u32.u64 %0, t; }"
        : "=r"(a) : "l"(p));
    return a;
}

__device__ __forceinline__ void cp_async16(uint32_t dst, const void* src) {
    asm volatile("cp.async.cg.shared.global [%0], [%1], 16;" :: "r"(dst), "l"(src));
}
#define CP_COMMIT() asm volatile("cp.async.commit_group;" ::: "memory")
#define CP_WAIT(n)  asm volatile("cp.async.wait_group %0;" :: "n"(n) : "memory")

__device__ __forceinline__ void ldsm_x4(uint32_t* r, uint32_t addr) {
    asm volatile("ldmatrix.sync.aligned.m8n8.x4.shared.b16 {%0,%1,%2,%3}, [%4];"
        : "=r"(r[0]), "=r"(r[1]), "=r"(r[2]), "=r"(r[3]) : "r"(addr));
}

__device__ __forceinline__ void mma_f16(float* c, const uint32_t* a,
                                        uint32_t b0, uint32_t b1) {
    asm volatile(
        "mma.sync.aligned.m16n8k16.row.col.f32.f16.f16.f32 "
        "{%0,%1,%2,%3}, {%4,%5,%6,%7}, {%8,%9}, {%0,%1,%2,%3};"
        : "+f"(c[0]), "+f"(c[1]), "+f"(c[2]), "+f"(c[3])
        : "r"(a[0]), "r"(a[1]), "r"(a[2]), "r"(a[3]), "r"(b0), "r"(b1));
}

__device__ __forceinline__ uint32_t h2u(__half2 h) {
    return *reinterpret_cast<uint32_t*>(&h);
}

// ---------------------------------------------------------------------------
// Kernel 1 (merged): blocks [0, GX_BLOCKS) convert X fp32->fp16;
// blocks [GX_BLOCKS, GX_BLOCKS+GW_BLOCKS) gather+convert W.
// Both are DRAM-bound; merging overlaps their memory streams.
// ---------------------------------------------------------------------------
__global__ void __launch_bounds__(256)
prep_operands(const float* __restrict__ x, const int* __restrict__ idx,
              const float* __restrict__ w) {
    unsigned b = blockIdx.x;
    if (b < GX_BLOCKS) {
        size_t i = (size_t)b * 256 + threadIdx.x;
        const float4* p = reinterpret_cast<const float4*>(x) + 2 * i;
        float4 a = p[0], c = p[1];
        uint4 o;
        o.x = h2u(__floats2half2_rn(a.x, a.y));
        o.y = h2u(__floats2half2_rn(a.z, a.w));
        o.z = h2u(__floats2half2_rn(c.x, c.y));
        o.w = h2u(__floats2half2_rn(c.z, c.w));
        reinterpret_cast<uint4*>(g_X)[i] = o;
    } else {
        size_t i = (size_t)(b - GX_BLOCKS) * 256 + threadIdx.x;
        const int4* ip = reinterpret_cast<const int4*>(idx) + 2 * i;
        int4 v0 = ip[0], v1 = ip[1];
        uint4 o;
        o.x = h2u(__floats2half2_rn(__ldg(w + v0.x), __ldg(w + v0.y)));
        o.y = h2u(__floats2half2_rn(__ldg(w + v0.z), __ldg(w + v0.w)));
        o.z = h2u(__floats2half2_rn(__ldg(w + v1.x), __ldg(w + v1.y)));
        o.w = h2u(__floats2half2_rn(__ldg(w + v1.z), __ldg(w + v1.w)));
        reinterpret_cast<uint4*>(g_Wh)[i] = o;
    }
}

// ---------------------------------------------------------------------------
// Kernel 2: fp16 mma.sync GEMM  Out[m,n] = sum_k X[m,k]*W[n,k] + bias[n]
// 256 threads = 8 warps, 2(M) x 4(N), warp tile 64x64. 3-stage cp.async.
// ---------------------------------------------------------------------------
extern "C" __global__ void __launch_bounds__(256, 1)
hashed_gemm(const float* __restrict__ bias, float* __restrict__ Out) {
    extern __shared__ __align__(16) unsigned char smem[];

    const int tid  = threadIdx.x;
    const int wid  = tid >> 5;
    const int lane = tid & 31;
    const int warp_m = wid & 1;           // 0..1 (64 M rows each)
    const int warp_n = wid >> 1;          // 0..3 (64 N cols each)
    const int qr = lane >> 2;             // 0..7
    const int qk = lane & 3;              // 0..3

    const int n0 = blockIdx.x * BN;
    const int m0 = blockIdx.y * BM;

    const uint32_t sb = smem_u32(smem);

    // cp.async: A tile 128 rows x 8 segs (1024), B tile 256 rows x 8 segs (2048)
    auto issue_chunk = [&](int c, int stage) {
        const uint32_t abase = sb + (uint32_t)(stage * STAGE_BYTES);
        const uint32_t bbase = abase + A_TILE_BYTES;
        const __half* gx = g_X  + (size_t)m0 * IN_F + c * BK;
        const __half* gw = g_Wh + (size_t)n0 * IN_F + c * BK;
#pragma unroll
        for (int t = 0; t < 4; t++) {
            int idx = tid + t * 256;           // 0..1023
            int row = idx >> 3;
            int seg = idx & 7;
            cp_async16(abase + (uint32_t)(row * ROW_BYTES + seg * 16),
                       gx + (size_t)row * IN_F + seg * 8);
        }
#pragma unroll
        for (int t = 0; t < 8; t++) {
            int idx = tid + t * 256;           // 0..2047
            int row = idx >> 3;
            int seg = idx & 7;
            cp_async16(bbase + (uint32_t)(row * ROW_BYTES + seg * 16),
                       gw + (size_t)row * IN_F + seg * 8);
        }
    };

    // ldmatrix per-lane base offsets (bytes within tile)
    // A x4: lanes 0-15 -> 16 rows @ k, lanes 16-31 -> same rows @ k+8 halves
    const uint32_t a_off = (uint32_t)((warp_m * 64 + (lane & 15)) * ROW_BYTES
                                      + (lane >> 4) * 16);
    // B x4 (per 16-row group): lanes 0-7 rows+0..7 @k, 8-15 rows+0..7 @k+8,
    //                          16-23 rows+8..15 @k, 24-31 rows+8..15 @k+8
    const uint32_t b_off = (uint32_t)((warp_n * 64 + (lane & 7) + ((lane >> 4) & 1) * 8) * ROW_BYTES
                                      + ((lane >> 3) & 1) * 16);

    // Prologue: fill STAGES-1 stages
#pragma unroll
    for (int c = 0; c < STAGES - 1; c++) {
        issue_chunk(c, c);
        CP_COMMIT();
    }

    float acc[4][8][4];
#pragma unroll
    for (int mt = 0; mt < 4; mt++)
#pragma unroll
        for (int nt = 0; nt < 8; nt++)
#pragma unroll
            for (int q = 0; q < 4; q++) acc[mt][nt][q] = 0.0f;

    for (int c = 0; c < NCHUNK; ++c) {
        CP_WAIT(STAGES - 2);
        __syncthreads();

        const int nk = c + STAGES - 1;
        if (nk < NCHUNK) issue_chunk(nk, nk % STAGES);
        CP_COMMIT();

        const uint32_t As = sb + (uint32_t)((c % STAGES) * STAGE_BYTES);
        const uint32_t Bs = As + A_TILE_BYTES;

#pragma unroll
        for (int kk = 0; kk < BK / 16; kk++) {        // 4 k16 steps
            const uint32_t kb = (uint32_t)(kk * 32);  // 16 halves = 32 B
            uint32_t af[4][4];
#pragma unroll
            for (int mt = 0; mt < 4; mt++)
                ldsm_x4(af[mt], As + a_off + (uint32_t)(mt * 16 * ROW_BYTES) + kb);
            uint32_t bf[4][4];
#pragma unroll
            for (int pr = 0; pr < 4; pr++)
                ldsm_x4(bf[pr], Bs + b_off + (uint32_t)(pr * 16 * ROW_BYTES) + kb);
#pragma unroll
            for (int nt = 0; nt < 8; nt++) {
                const uint32_t b0 = bf[nt >> 1][(nt & 1) * 2];
                const uint32_t b1 = bf[nt >> 1][(nt & 1) * 2 + 1];
#pragma unroll
                for (int mt = 0; mt < 4; mt++)
                    mma_f16(acc[mt][nt], af[mt], b0, b1);
            }
        }
    }

    // Epilogue: add bias, store float2 per (row, nt)
#pragma unroll
    for (int mt = 0; mt < 4; mt++) {
        const int r = m0 + warp_m * 64 + mt * 16 + qr;
#pragma unroll
        for (int nt = 0; nt < 8; nt++) {
            const int col = n0 + warp_n * 64 + nt * 8 + 2 * qk;
            const float bx = __ldg(bias + col);
            const float by = __ldg(bias + col + 1);
            float2 v0 = make_float2(acc[mt][nt][0] + bx, acc[mt][nt][1] + by);
            float2 v1 = make_float2(acc[mt][nt][2] + bx, acc[mt][nt][3] + by);
            *reinterpret_cast<float2*>(Out + (size_t)r * OUT_F + col) = v0;
            *reinterpret_cast<float2*>(Out + (size_t)(r + 8) * OUT_F + col) = v1;
        }
    }
}

// ---------------------------------------------------------------------------
// Launch
// ---------------------------------------------------------------------------
extern "C" void kernel_launch(void* const* d_in, const int* in_sizes, int n_in,
                              void* d_out, int out_size) {
    const float* x    = (const float*)d_in[0];   // [8192, 4096] f32
    const float* w    = (const float*)d_in[1];   // [65536] f32
    const float* bias = (const float*)d_in[2];   // [4096] f32
    const int*   idx  = (const int*)d_in[3];     // [4096*4096] i32
    float* out = (float*)d_out;                  // [8192, 4096] f32

    static bool attr_set = false;
    if (!attr_set) {
        cudaFuncSetAttribute(hashed_gemm,
                             cudaFuncAttributeMaxDynamicSharedMemorySize, SMEM_BYTES);
        attr_set = true;
    }

    // Stage 1: convert X and gather/convert W in one overlapped launch.
    prep_operands<<<GX_BLOCKS + GW_BLOCKS, 256>>>(x, idx, w);

    // Stage 2: fp16 tensor-core GEMM + bias epilogue.
    dim3 grid(OUT_F / BN, TOKENS_N / BM);                    // (16, 64)
    hashed_gemm<<<grid, 256, SMEM_BYTES>>>(bias, out);
}

// round 12
// speedup vs baseline: 1.2390x; 1.2390x over previous
#include <cuda_runtime.h>
#include <cuda_fp16.h>
#include <cstdint>
#include <cstddef>

// Problem dims
#define TOKENS_N 8192
#define IN_F     4096
#define OUT_F    4096

// GEMM tiling: CTA 128x128, warp 64x32, BK=64 halves (128B/row)
#define BM      128
#define BN      128
#define BK      64
#define STAGES  3
#define NCHUNK  (IN_F / BK)            // 64

// smem: 128B rows with XOR swizzle (seg ^= row&7) -> conflict-free for both
// cp.async 16B stores and ldmatrix 8-row phases; no padding needed.
#define ROW_BYTES    128
#define A_TILE_BYTES (BM * ROW_BYTES)                 // 16384
#define B_TILE_BYTES (BN * ROW_BYTES)                 // 16384
#define STAGE_BYTES  (A_TILE_BYTES + B_TILE_BYTES)    // 32768
#define SMEM_BYTES   (STAGES * STAGE_BYTES)           // 98304 -> 2 CTAs/SM

// Pre-converted operands (device globals: allowed scratch)
__device__ __half g_X [(size_t)TOKENS_N * IN_F];   // 64 MB
__device__ __half g_Wh[(size_t)OUT_F   * IN_F];    // 32 MB

#define GX_BLOCKS ((unsigned)(((size_t)TOKENS_N * IN_F / 8) / 256))   // 16384
#define GW_BLOCKS ((unsigned)(((size_t)OUT_F   * IN_F / 8) / 256))    // 8192

// ---------------------------------------------------------------------------
// helpers
// ---------------------------------------------------------------------------
__device__ __forceinline__ uint32_t smem_u32(const void* p) {
    uint32_t a;
    asm("{ .reg .u64 t; cvta.to.shared.u64 t, %1; cvt.u32.u64 %0, t; }"
        : "=r"(a) : "l"(p));
    return a;
}

__device__ __forceinline__ void cp_async16(uint32_t dst, const void* src) {
    asm volatile("cp.async.cg.shared.global [%0], [%1], 16;" :: "r"(dst), "l"(src));
}
#define CP_COMMIT() asm volatile("cp.async.commit_group;" ::: "memory")
#define CP_WAIT(n)  asm volatile("cp.async.wait_group %0;" :: "n"(n) : "memory")

__device__ __forceinline__ void ldsm_x4(uint32_t* r, uint32_t addr) {
    asm volatile("ldmatrix.sync.aligned.m8n8.x4.shared.b16 {%0,%1,%2,%3}, [%4];"
        : "=r"(r[0]), "=r"(r[1]), "=r"(r[2]), "=r"(r[3]) : "r"(addr));
}

__device__ __forceinline__ void mma_f16(float* c, const uint32_t* a,
                                        uint32_t b0, uint32_t b1) {
    asm volatile(
        "mma.sync.aligned.m16n8k16.row.col.f32.f16.f16.f32 "
        "{%0,%1,%2,%3}, {%4,%5,%6,%7}, {%8,%9}, {%0,%1,%2,%3};"
        : "+f"(c[0]), "+f"(c[1]), "+f"(c[2]), "+f"(c[3])
        : "r"(a[0]), "r"(a[1]), "r"(a[2]), "r"(a[3]), "r"(b0), "r"(b1));
}

__device__ __forceinline__ uint32_t h2u(__half2 h) {
    return *reinterpret_cast<uint32_t*>(&h);
}

// ---------------------------------------------------------------------------
// Kernel 1 (merged): blocks [0, GX_BLOCKS) convert X fp32->fp16;
// blocks [GX_BLOCKS, GX_BLOCKS+GW_BLOCKS) gather+convert W.
// ---------------------------------------------------------------------------
__global__ void __launch_bounds__(256)
prep_operands(const float* __restrict__ x, const int* __restrict__ idx,
              const float* __restrict__ w) {
    unsigned b = blockIdx.x;
    if (b < GX_BLOCKS) {
        size_t i = (size_t)b * 256 + threadIdx.x;
        const float4* p = reinterpret_cast<const float4*>(x) + 2 * i;
        float4 a = p[0], c = p[1];
        uint4 o;
        o.x = h2u(__floats2half2_rn(a.x, a.y));
        o.y = h2u(__floats2half2_rn(a.z, a.w));
        o.z = h2u(__floats2half2_rn(c.x, c.y));
        o.w = h2u(__floats2half2_rn(c.z, c.w));
        reinterpret_cast<uint4*>(g_X)[i] = o;
    } else {
        size_t i = (size_t)(b - GX_BLOCKS) * 256 + threadIdx.x;
        const int4* ip = reinterpret_cast<const int4*>(idx) + 2 * i;
        int4 v0 = ip[0], v1 = ip[1];
        uint4 o;
        o.x = h2u(__floats2half2_rn(__ldg(w + v0.x), __ldg(w + v0.y)));
        o.y = h2u(__floats2half2_rn(__ldg(w + v0.z), __ldg(w + v0.w)));
        o.z = h2u(__floats2half2_rn(__ldg(w + v1.x), __ldg(w + v1.y)));
        o.w = h2u(__floats2half2_rn(__ldg(w + v1.z), __ldg(w + v1.w)));
        reinterpret_cast<uint4*>(g_Wh)[i] = o;
    }
}

// ---------------------------------------------------------------------------
// Kernel 2: fp16 mma.sync GEMM  Out[m,n] = sum_k X[m,k]*W[n,k] + bias[n]
// 256 threads = 8 warps, 2(M) x 4(N), warp tile 64x32.
// 3-stage cp.async pipeline + register double-buffered fragments.
// ---------------------------------------------------------------------------
extern "C" __global__ void __launch_bounds__(256, 2)
hashed_gemm(const float* __restrict__ bias, float* __restrict__ Out) {
    extern __shared__ __align__(16) unsigned char smem[];

    const int tid  = threadIdx.x;
    const int wid  = tid >> 5;
    const int lane = tid & 31;
    const int warp_m = wid >> 2;          // 0..1
    const int warp_n = wid & 3;           // 0..3
    const int qr = lane >> 2;             // 0..7
    const int qk = lane & 3;              // 0..3

    const int n0 = blockIdx.x * BN;
    const int m0 = blockIdx.y * BM;

    const uint32_t sb = smem_u32(smem);

    // cp.async: tile = 128 rows x 8 x 16B segments (1024); 4 A + 4 B per thread
    auto issue_chunk = [&](int c, int stage) {
        const uint32_t abase = sb + (uint32_t)(stage * STAGE_BYTES);
        const uint32_t bbase = abase + A_TILE_BYTES;
        const __half* gx = g_X  + (size_t)m0 * IN_F + c * BK;
        const __half* gw = g_Wh + (size_t)n0 * IN_F + c * BK;
#pragma unroll
        for (int t = 0; t < 4; t++) {
            int idx = tid + t * 256;           // 0..1023
            int row = idx >> 3;
            int seg = idx & 7;
            uint32_t soff = (uint32_t)(row * ROW_BYTES + ((seg ^ (row & 7)) * 16));
            cp_async16(abase + soff, gx + (size_t)row * IN_F + seg * 8);
            cp_async16(bbase + soff, gw + (size_t)row * IN_F + seg * 8);
        }
    };

    // ldmatrix per-lane addressing (XOR swizzle, seg ^= row&7)
    // A x4: 16 rows (lane&15), col half = (lane>>4); row&7 invariant under +16*mt
    const int      a_row = warp_m * 64 + (lane & 15);
    const uint32_t a_sel = (uint32_t)(lane >> 4);
    // B x4: rows (lane&7) + ((lane>>4)&1)*8, col half = (lane>>3)&1
    const int      b_row = warp_n * 32 + (lane & 7) + ((lane >> 4) & 1) * 8;
    const uint32_t b_sel = (uint32_t)((lane >> 3) & 1);
    const uint32_t lxor  = (uint32_t)(lane & 7);   // row&7 for both A and B lanes

    auto a_addr = [&](uint32_t As, int mt, int kk) {
        return As + (uint32_t)((a_row + mt * 16) * ROW_BYTES)
                  + ((((uint32_t)kk * 2 + a_sel) ^ lxor) * 16);
    };
    auto b_addr = [&](uint32_t Bs, int pr, int kk) {
        return Bs + (uint32_t)((b_row + pr * 16) * ROW_BYTES)
                  + ((((uint32_t)kk * 2 + b_sel) ^ lxor) * 16);
    };

    // Prologue: fill STAGES-1 stages
#pragma unroll
    for (int c = 0; c < STAGES - 1; c++) {
        issue_chunk(c, c);
        CP_COMMIT();
    }

    float acc[4][4][4];
#pragma unroll
    for (int mt = 0; mt < 4; mt++)
#pragma unroll
        for (int nt = 0; nt < 4; nt++)
#pragma unroll
            for (int q = 0; q < 4; q++) acc[mt][nt][q] = 0.0f;

    uint32_t af[2][4][4];
    uint32_t bf[2][2][4];

    for (int c = 0; c < NCHUNK; ++c) {
        CP_WAIT(STAGES - 2);
        __syncthreads();

        const uint32_t As = sb + (uint32_t)((c % STAGES) * STAGE_BYTES);
        const uint32_t Bs = As + A_TILE_BYTES;

        // kk=0 fragments into buffer 0 (only exposed ldsm latency per chunk)
#pragma unroll
        for (int mt = 0; mt < 4; mt++) ldsm_x4(af[0][mt], a_addr(As, mt, 0));
#pragma unroll
        for (int pr = 0; pr < 2; pr++) ldsm_x4(bf[0][pr], b_addr(Bs, pr, 0));

        // issue next chunk's loads while kk=0 fragments are in flight
        const int nk = c + STAGES - 1;
        if (nk < NCHUNK) issue_chunk(nk, nk % STAGES);
        CP_COMMIT();

#pragma unroll
        for (int kk = 0; kk < BK / 16; kk++) {        // 4 k16 steps
            const int cur = kk & 1;
            const int nxt = cur ^ 1;
            if (kk < BK / 16 - 1) {                   // prefetch kk+1 fragments
#pragma unroll
                for (int mt = 0; mt < 4; mt++)
                    ldsm_x4(af[nxt][mt], a_addr(As, mt, kk + 1));
#pragma unroll
                for (int pr = 0; pr < 2; pr++)
                    ldsm_x4(bf[nxt][pr], b_addr(Bs, pr, kk + 1));
            }
#pragma unroll
            for (int nt = 0; nt < 4; nt++) {
                const uint32_t b0 = bf[cur][nt >> 1][(nt & 1) * 2];
                const uint32_t b1 = bf[cur][nt >> 1][(nt & 1) * 2 + 1];
#pragma unroll
                for (int mt = 0; mt < 4; mt++)
                    mma_f16(acc[mt][nt], af[cur][mt], b0, b1);
            }
        }
    }

    // Epilogue: add bias, store float2 per (row, nt)
#pragma unroll
    for (int mt = 0; mt < 4; mt++) {
        const int r = m0 + warp_m * 64 + mt * 16 + qr;
#pragma unroll
        for (int nt = 0; nt < 4; nt++) {
            const int col = n0 + warp_n * 32 + nt * 8 + 2 * qk;
            const float bx = __ldg(bias + col);
            const float by = __ldg(bias + col + 1);
            float2 v0 = make_float2(acc[mt][nt][0] + bx, acc[mt][nt][1] + by);
            float2 v1 = make_float2(acc[mt][nt][2] + bx, acc[mt][nt][3] + by);
            *reinterpret_cast<float2*>(Out + (size_t)r * OUT_F + col) = v0;
            *reinterpret_cast<float2*>(Out + (size_t)(r + 8) * OUT_F + col) = v1;
        }
    }
}

// ---------------------------------------------------------------------------
// Launch
// ---------------------------------------------------------------------------
extern "C" void kernel_launch(void* const* d_in, const int* in_sizes, int n_in,
                              void* d_out, int out_size) {
    const float* x    = (const float*)d_in[0];   // [8192, 4096] f32
    const float* w    = (const float*)d_in[1];   // [65536] f32
    const float* bias = (const float*)d_in[2];   // [4096] f32
    const int*   idx  = (const int*)d_in[3];     // [4096*4096] i32
    float* out = (float*)d_out;                  // [8192, 4096] f32

    static bool attr_set = false;
    if (!attr_set) {
        cudaFuncSetAttribute(hashed_gemm,
                             cudaFuncAttributeMaxDynamicSharedMemorySize, SMEM_BYTES);
        attr_set = true;
    }

    // Stage 1: convert X and gather/convert W in one overlapped launch.
    prep_operands<<<GX_BLOCKS + GW_BLOCKS, 256>>>(x, idx, w);

    // Stage 2: fp16 tensor-core GEMM + bias epilogue.
    dim3 grid(OUT_F / BN, TOKENS_N / BM);                    // (32, 64)
    hashed_gemm<<<grid, 256, SMEM_BYTES>>>(bias, out);
}